// round 9
// baseline (speedup 1.0000x reference)
#include <cuda_runtime.h>
#include <cuda_bf16.h>
#include <math.h>
#include <stdint.h>

// Problem constants (fixed by the dataset)
#define B_   16384
#define E_   128
#define S_   512
#define VOC_ 1000000

#define NBLK 512                      // 128 row-tiles x 4 col-tiles (true rows fused)
#define TILE_BYTES 32768              // 128 rows x 128 bf16 (256B/row)
#define DYN_SMEM (2 * TILE_BYTES)

// ---- device scratch (no allocations allowed) ----
__device__ uint32_t g_Asw[128 * TILE_BYTES / 4]; // pre-swizzled bf16 A tiles (4MB)
__device__ uint32_t g_Bsw[4 * TILE_BYTES / 4];   // pre-swizzled bf16 B tiles
__device__ float g_corr[S_];
__device__ float g_tcorr[B_];
__device__ float g_part_samp[NBLK];
__device__ float g_part_true[NBLK];
__device__ int   g_idx64;
__device__ unsigned int g_done;       // zero-init; reset by last block each run

__device__ __forceinline__ uint32_t smem_u32(const void* p) {
    uint32_t a;
    asm("{ .reg .u64 t; cvta.to.shared.u64 t, %1; cvt.u32.u64 %0, t; }"
        : "=r"(a) : "l"(p));
    return a;
}

// Swizzled tile layout: [row r][16B chunk c], phys chunk = c ^ (r&7).
__device__ __forceinline__ uint32_t tile_off(int r, int c) {
    return (uint32_t)(r * 256 + ((c ^ (r & 7)) << 4));
}

// -------------------------------------------------------------------------
// Index dtype detection (per-block, scans first 256 int64 words = 2KB, safe
// for both int32[512] and int64[512] buffers). If the data is int32, the
// high half of each word is the next random id (~never all zero) => OOB.
// -------------------------------------------------------------------------
__device__ __forceinline__ int detect64(const void* sampled, int tid, int* sh) {
    if (tid == 0) *sh = 0;
    __syncthreads();
    const long long* s64 = (const long long*)sampled;
    for (int i = tid; i < 256; i += blockDim.x) {
        long long v = s64[i];
        if (v < 0 || v >= VOC_) *sh = 1;
    }
    __syncthreads();
    return *sh ? 0 : 1;
}
__device__ __forceinline__ int load_id(const void* p, int i, int idx64) {
    long long v;
    if (idx64) v = ((const long long*)p)[i];
    else       v = (long long)((const int*)p)[i];
    if (v < 0) v = 0;
    if (v >= VOC_) v = VOC_ - 1;
    return (int)v;
}

// -------------------------------------------------------------------------
// Reference-faithful  -log(expected_count(id))  (cancellation-safe)
// -------------------------------------------------------------------------
__device__ __forceinline__ float neg_log_expected(int id) {
    double cd = (double)id;
    float l2 = (float)log(cd + 2.0);
    float l1 = (float)log(cd + 1.0);
    float denom = (float)log((double)VOC_ + 1.0);
    float p = (l2 - l1) / denom;
    float lp = log1pf(-p);
    float e  = -expm1f(512.0f * lp);
    return -logf(e);
}

// -------------------------------------------------------------------------
// Fast softplus: max(x,0) + log1p(exp(-|x|)); FMA/ALU hot path.
// -------------------------------------------------------------------------
__device__ __forceinline__ float softplus_fast(float x) {
    float u  = fabsf(x);
    float mx = fmaxf(x, 0.0f);
    float y  = fmaxf(u * -1.4426950408889634f, -25.0f);
    int   n  = __float2int_rn(y);
    float f  = y - (float)n;
    float pe = 1.3333558146e-3f;
    pe = fmaf(pe, f, 9.6181291076e-3f);
    pe = fmaf(pe, f, 5.5504108665e-2f);
    pe = fmaf(pe, f, 2.4022650696e-1f);
    pe = fmaf(pe, f, 6.9314718056e-1f);
    pe = fmaf(pe, f, 1.0f);
    float t = pe * __int_as_float((n + 127) << 23);
    float l;
    if (t > 0.125f) {
        l = log1pf(t);
    } else {
        l = t * fmaf(t, fmaf(t, fmaf(t, -0.25f, 0.33333333f), -0.5f), 1.0f);
    }
    return mx + l;
}

__device__ __forceinline__ uint32_t pack_bf(float a, float b) {
    __nv_bfloat162 h = __floats2bfloat162_rn(a, b);
    return *reinterpret_cast<uint32_t*>(&h);
}

// -------------------------------------------------------------------------
// K_prep (256 thr): bx [0,32)   gather B rows -> swizzled bf16 + corr
//                   bx [32,96)  per-label corr (fp64 logs, fully parallel)
//                   bx [96,224) convert A tiles -> swizzled bf16 (g_Asw)
// -------------------------------------------------------------------------
__global__ void k_prep(const float* __restrict__ P, const float* __restrict__ W,
                       const float* __restrict__ bias,
                       const void* __restrict__ sampled,
                       const void* __restrict__ labels) {
    __shared__ int shf;
    int bx = blockIdx.x, t = threadIdx.x;
    if (bx < 32) {
        int idx64 = detect64(sampled, t, &shf);
        if (bx == 0 && t == 0) g_idx64 = idx64;
        int sl = t >> 4;                 // 0..15 sample within block
        int kg = t & 15;                 // 16B k-chunk
        int s  = bx * 16 + sl;
        int id = load_id(sampled, s, idx64);
        const float* src = W + (size_t)id * E_ + kg * 8;
        float4 v0 = *(const float4*)src;
        float4 v1 = *(const float4*)(src + 4);
        uint4 u;
        u.x = pack_bf(v0.x, v0.y); u.y = pack_bf(v0.z, v0.w);
        u.z = pack_bf(v1.x, v1.y); u.w = pack_bf(v1.z, v1.w);
        int colTile = s >> 7, n = s & 127;
        *(uint4*)((char*)g_Bsw + colTile * TILE_BYTES + tile_off(n, kg)) = u;
        if (kg == 0)
            g_corr[s] = bias[id] + neg_log_expected(id);
    } else if (bx < 96) {
        int idx64 = detect64(sampled, t, &shf);
        int i = (bx - 32) * 256 + t;
        int id = load_id(labels, i, idx64);
        g_tcorr[i] = bias[id] + neg_log_expected(id);
    } else {
        int rowTile = bx - 96;
        const float* Abase = P + (size_t)rowTile * 128 * E_;
        char* dst = (char*)g_Asw + (size_t)rowTile * TILE_BYTES;
#pragma unroll
        for (int i = 0; i < 8; i++) {
            int gidx = t + 256 * i;              // 0..2047
            int r = gidx >> 4, c = gidx & 15;
            const float* src = Abase + (size_t)r * E_ + c * 8;
            float4 v0 = *(const float4*)src;
            float4 v1 = *(const float4*)(src + 4);
            uint4 u;
            u.x = pack_bf(v0.x, v0.y); u.y = pack_bf(v0.z, v0.w);
            u.z = pack_bf(v1.x, v1.y); u.w = pack_bf(v1.z, v1.w);
            *(uint4*)(dst + tile_off(r, c)) = u;
        }
    }
}

#define LDMX4(r0, r1, r2, r3, addr) \
    asm volatile("ldmatrix.sync.aligned.m8n8.x4.shared.b16 {%0,%1,%2,%3}, [%4];" \
                 : "=r"(r0), "=r"(r1), "=r"(r2), "=r"(r3) : "r"(addr))

#define MMA16816(c, a, b0, b1) \
    asm volatile("mma.sync.aligned.m16n8k16.row.col.f32.bf16.bf16.f32 " \
                 "{%0,%1,%2,%3}, {%4,%5,%6,%7}, {%8,%9}, {%0,%1,%2,%3};" \
                 : "+f"((c)[0]), "+f"((c)[1]), "+f"((c)[2]), "+f"((c)[3]) \
                 : "r"((a)[0]), "r"((a)[1]), "r"((a)[2]), "r"((a)[3]), \
                   "r"(b0), "r"(b1))

// -------------------------------------------------------------------------
// K_main: 512 blocks; each does one 128x128 GEMM tile + softplus + 32 true
// rows + (last block) deterministic final reduction.
// block = 256 threads (8 warps, 4x2), warp tile 32x64, dyn smem = 64KB
// -------------------------------------------------------------------------
__global__ __launch_bounds__(256, 2)
void k_main(const float* __restrict__ P, const float* __restrict__ W,
            const void* __restrict__ labels, float* __restrict__ out) {
    __shared__ float red[256];
    __shared__ double dred[256];
    __shared__ unsigned int ticket;
    extern __shared__ char dyn[];

    const int bx = blockIdx.x;
    const int tid = threadIdx.x, lane = tid & 31, wid = tid >> 5;
    const int rowTile = bx >> 2, colTile = bx & 3;

    char* Abuf = dyn;
    char* Bbuf = dyn + TILE_BYTES;

    // Stage both tiles: pure 16B copies (pre-converted & pre-swizzled)
    const uint4* Asrc = (const uint4*)((const char*)g_Asw + (size_t)rowTile * TILE_BYTES);
    const uint4* Bsrc = (const uint4*)((const char*)g_Bsw + colTile * TILE_BYTES);
#pragma unroll
    for (int i = 0; i < 8; i++) {
        ((uint4*)Abuf)[tid + 256 * i] = Asrc[tid + 256 * i];
        ((uint4*)Bbuf)[tid + 256 * i] = Bsrc[tid + 256 * i];
    }
    __syncthreads();

    const int warpRow = wid & 3;          // m offset *32
    const int warpCol = wid >> 2;         // n offset *64
    const int lrow = lane & 15;
    const int lhi  = lane >> 4;           // k-chunk parity for ldmatrix

    const uint32_t a_s = smem_u32(Abuf);
    const uint32_t b_s = smem_u32(Bbuf);

    int arow[2], brow[4];
#pragma unroll
    for (int mi = 0; mi < 2; mi++) arow[mi] = warpRow * 32 + mi * 16 + lrow;
#pragma unroll
    for (int nj = 0; nj < 4; nj++) brow[nj] = warpCol * 64 + nj * 16 + lrow;

    float acc[2][8][4];
#pragma unroll
    for (int mi = 0; mi < 2; mi++)
#pragma unroll
        for (int ni = 0; ni < 8; ni++)
#pragma unroll
            for (int r = 0; r < 4; r++) acc[mi][ni][r] = 0.0f;

#pragma unroll
    for (int ks = 0; ks < 8; ks++) {
        const int chunk = ks * 2 + lhi;
        uint32_t a[2][4];
#pragma unroll
        for (int mi = 0; mi < 2; mi++) {
            uint32_t addr = a_s + (uint32_t)(arow[mi] * 256
                           + ((chunk ^ (arow[mi] & 7)) << 4));
            LDMX4(a[mi][0], a[mi][1], a[mi][2], a[mi][3], addr);
        }
        uint32_t bb[4][4];
#pragma unroll
        for (int nj = 0; nj < 4; nj++) {
            uint32_t addr = b_s + (uint32_t)(brow[nj] * 256
                           + ((chunk ^ (brow[nj] & 7)) << 4));
            LDMX4(bb[nj][0], bb[nj][1], bb[nj][2], bb[nj][3], addr);
        }
#pragma unroll
        for (int mi = 0; mi < 2; mi++)
#pragma unroll
            for (int ni = 0; ni < 8; ni++)
                MMA16816(acc[mi][ni], a[mi],
                         bb[ni >> 1][ni & 1], bb[ni >> 1][2 + (ni & 1)]);
    }

    // Epilogue: cols warpCol*64+ni*8+q*2(+1), q=lane&3
    const int q = lane & 3;
    const float* corrB = g_corr + colTile * 128 + warpCol * 64;
    float lsum = 0.0f;
#pragma unroll
    for (int ni = 0; ni < 8; ni++) {
        float c0 = corrB[ni * 8 + q * 2];
        float c1 = corrB[ni * 8 + q * 2 + 1];
#pragma unroll
        for (int mi = 0; mi < 2; mi++) {
            lsum += softplus_fast(acc[mi][ni][0] + c0);
            lsum += softplus_fast(acc[mi][ni][1] + c1);
            lsum += softplus_fast(acc[mi][ni][2] + c0);
            lsum += softplus_fast(acc[mi][ni][3] + c1);
        }
    }
    red[tid] = lsum;
    __syncthreads();
#pragma unroll
    for (int s = 128; s > 0; s >>= 1) {
        if (tid < s) red[tid] += red[tid + s];
        __syncthreads();
    }
    if (tid == 0) g_part_samp[bx] = red[0];
    __syncthreads();

    // True-class rows: this block owns rows bx*32 .. bx*32+31 (warp: 4 rows)
    const int idx64 = g_idx64;
    float wsum = 0.0f;
#pragma unroll
    for (int i = 0; i < 4; i++) {
        int row = bx * 32 + wid * 4 + i;
        int id = load_id(labels, row, idx64);
        float4 p4 = *(const float4*)(P + (size_t)row * E_ + lane * 4);
        float4 w4 = *(const float4*)(W + (size_t)id  * E_ + lane * 4);
        float d = p4.x * w4.x + p4.y * w4.y + p4.z * w4.z + p4.w * w4.w;
#pragma unroll
        for (int off = 16; off > 0; off >>= 1)
            d += __shfl_xor_sync(0xFFFFFFFFu, d, off);
        if (lane == 0) {
            float x = d + g_tcorr[row];
            wsum += softplus_fast(x) - x;   // sce(x, z=1)
        }
    }
    red[tid] = (lane == 0) ? wsum : 0.0f;
    __syncthreads();
#pragma unroll
    for (int s = 128; s > 0; s >>= 1) {
        if (tid < s) red[tid] += red[tid + s];
        __syncthreads();
    }
    if (tid == 0) g_part_true[bx] = red[0];

    // Last-block deterministic final reduction
    __threadfence();
    if (tid == 0) ticket = atomicAdd(&g_done, 1u);
    __syncthreads();
    if (ticket == NBLK - 1) {
        __threadfence();
        double s = 0.0;
        for (int i = tid; i < NBLK; i += 256)
            s += (double)g_part_samp[i] + (double)g_part_true[i];
        dred[tid] = s;
        __syncthreads();
#pragma unroll
        for (int k = 128; k > 0; k >>= 1) {
            if (tid < k) dred[tid] += dred[tid + k];
            __syncthreads();
        }
        if (tid == 0) {
            out[0] = (float)(dred[0] / (double)B_);
            g_done = 0;                  // reset for next graph replay
        }
    }
}

// -------------------------------------------------------------------------
extern "C" void kernel_launch(void* const* d_in, const int* in_sizes, int n_in,
                              void* d_out, int out_size) {
    const float* pred    = (const float*)d_in[0];   // [B, E]
    const float* weights = (const float*)d_in[1];   // [V, E]
    const float* biases  = (const float*)d_in[2];   // [V]
    const void*  labels  = d_in[3];                 // [B, 1] int32 or int64
    const void*  sampled = d_in[4];                 // [S]
    float* out = (float*)d_out;

    static int attr_done = 0;
    if (!attr_done) {
        cudaFuncSetAttribute(k_main, cudaFuncAttributeMaxDynamicSharedMemorySize,
                             DYN_SMEM);
        attr_done = 1;
    }

    k_prep<<<224, 256>>>(pred, weights, biases, sampled, labels);
    k_main<<<NBLK, 256, DYN_SMEM>>>(pred, weights, labels, out);
}